// round 5
// baseline (speedup 1.0000x reference)
#include <cuda_runtime.h>
#include <math.h>

#define BB 4
#define LL 512
#define VV 32128
#define AVV 32000
#define DD 768
#define NT (BB*LL)
#define NV4 (VV/4)      // 8032
#define ND4 (DD/4)      // 192
#define NTH 256
#define CH 4            // chunks per token
#define CV4 (NV4/CH)    // 2008 float4 per chunk

// Scratch
__device__ int4 g_part[NT * CH];   // per (token,chunk) top-2: {bits(v1),i1,bits(v2),i2}
__device__ int  g_am[NT];          // final embed row (-1 = masked)
__device__ int  g_ps[NT];          // psg row (-1 = none)

// ---------------------------------------------------------------------------
// Exact coarse key: lo - log(-log u), series path near u=1 (winning tokens
// have u ~ 1-3e-5 where __logf's absolute error would be catastrophic).
// ---------------------------------------------------------------------------
__device__ __forceinline__ float coarse_key(float lo, float u) {
    float w  = 1.0f - u;                 // exact for u > 0.5 (Sterbenz)
    float ts = fmaf(0.5f * w, w, w);     // w + w^2/2
    float tl = -__logf(u);
    float t  = (u > 0.99609375f) ? ts : tl;
    return lo - __logf(t);
}

__device__ __forceinline__ double precise_key(float lo, float u) {
    return (double)lo - log(-log((double)u));
}

__device__ __forceinline__ void ins2(float k, int j,
                                     float& v1, int& i1,
                                     float& v2, int& i2) {
    bool p = k > v1;
    float dv = p ? v1 : k;
    int   di = p ? i1 : j;
    if (p) { v1 = k; i1 = j; }
    if (dv > v2) { v2 = dv; i2 = di; }
}

__device__ __forceinline__ void top2_insert(float w, int j,
                                            float& v1, int& i1,
                                            float& v2, int& i2) {
    if (w > v1 || (w == v1 && j < i1)) {
        v2 = v1; i2 = i1; v1 = w; i1 = j;
    } else if (w > v2 || (w == v2 && j < i2)) {
        v2 = w; i2 = j;
    }
}

// ---------------------------------------------------------------------------
// K1: streaming scan (unchanged — ~6.3 TB/s, near LTS ceiling).
// ---------------------------------------------------------------------------
__global__ void __launch_bounds__(NTH)
scan_kernel(const float* __restrict__ logits,
            const float* __restrict__ gu) {
    const int blk = blockIdx.x;
    const int t   = blk >> 2;
    const int c   = blk & 3;
    const int tid = threadIdx.x;

    const float4* lg = (const float4*)(logits + (size_t)t * VV) + c * CV4;
    const float4* gg = (const float4*)(gu     + (size_t)t * VV) + c * CV4;
    const int jbase = c * CV4 * 4;

    float v1 = -INFINITY, v2 = -INFINITY;
    int   i1 = 0,         i2 = 1;

    // seed: one exact float4 per lane, warp-wide 2nd-max -> thr
    {
        float4 a = __ldcs(lg + tid);
        float4 g = __ldcs(gg + tid);
        int base = jbase + 4 * tid;
        ins2(coarse_key(a.x, g.x), base + 0, v1, i1, v2, i2);
        ins2(coarse_key(a.y, g.y), base + 1, v1, i1, v2, i2);
        ins2(coarse_key(a.z, g.z), base + 2, v1, i1, v2, i2);
        ins2(coarse_key(a.w, g.w), base + 3, v1, i1, v2, i2);
    }
    float sa = v1, sb = v2;
#pragma unroll
    for (int off = 16; off > 0; off >>= 1) {
        float oa = __shfl_xor_sync(0xFFFFFFFFu, sa, off);
        float ob = __shfl_xor_sync(0xFFFFFFFFu, sb, off);
        float hi  = fmaxf(sa, oa);
        float lo2 = fmaxf(fminf(sa, oa), fmaxf(sb, ob));
        sa = hi; sb = lo2;
    }
    float thr = fmaxf(v2, sb);   // provable lower bound on global #2

    const float CB  = 88.029693f;       // 127 * ln2
    const float CC  = 8.2629582e-8f;    // ln2 / 2^23
    const float EPS = 1e-5f;            // I2F rounding margin

    for (int i = tid + NTH; i < CV4; i += NTH) {
        float4 a = __ldcs(lg + i);
        float4 g = __ldcs(gg + i);
        // one-sided bit-log upper bound: key <= lo - ln2*l2a(1-u)
        float ub0 = fmaf(-CC, (float)__float_as_int(1.0f - g.x), a.x + CB + EPS);
        float ub1 = fmaf(-CC, (float)__float_as_int(1.0f - g.y), a.y + CB + EPS);
        float ub2 = fmaf(-CC, (float)__float_as_int(1.0f - g.z), a.z + CB + EPS);
        float ub3 = fmaf(-CC, (float)__float_as_int(1.0f - g.w), a.w + CB + EPS);
        if (ub0 > thr || ub1 > thr || ub2 > thr || ub3 > thr) {
            int base = jbase + 4 * i;
            ins2(coarse_key(a.x, g.x), base + 0, v1, i1, v2, i2);
            ins2(coarse_key(a.y, g.y), base + 1, v1, i1, v2, i2);
            ins2(coarse_key(a.z, g.z), base + 2, v1, i1, v2, i2);
            ins2(coarse_key(a.w, g.w), base + 3, v1, i1, v2, i2);
            thr = fmaxf(thr, v2);
        }
    }

    __shared__ float s_v1[NTH]; __shared__ int s_i1[NTH];
    __shared__ float s_v2[NTH]; __shared__ int s_i2[NTH];
    s_v1[tid] = v1; s_i1[tid] = i1;
    s_v2[tid] = v2; s_i2[tid] = i2;
    __syncthreads();
    for (int s = NTH / 2; s > 0; s >>= 1) {
        if (tid < s) {
            float w1 = s_v1[tid + s], w2 = s_v2[tid + s];
            int   j1 = s_i1[tid + s], j2 = s_i2[tid + s];
            float a1 = s_v1[tid],     a2 = s_v2[tid];
            int   c1 = s_i1[tid],     c2 = s_i2[tid];
            top2_insert(w1, j1, a1, c1, a2, c2);
            top2_insert(w2, j2, a1, c1, a2, c2);
            s_v1[tid] = a1; s_i1[tid] = c1;
            s_v2[tid] = a2; s_i2[tid] = c2;
        }
        __syncthreads();
    }
    if (tid == 0) {
        g_part[blk] = make_int4(__float_as_int(s_v1[0]), s_i1[0],
                                __float_as_int(s_v2[0]), s_i2[0]);
    }
}

// ---------------------------------------------------------------------------
// K2: decide. grid=BB, block=LL. One thread per token; shift/firstnz once
// per batch. Pre-folds rwrt/AV mask into g_am so K3 has no logic.
// ---------------------------------------------------------------------------
__global__ void __launch_bounds__(LL)
decide_kernel(const float* __restrict__ logits,
              const float* __restrict__ gu,
              const int*   __restrict__ rwrt,
              const int*   __restrict__ psg_in) {
    const int b = blockIdx.x;
    const int l = threadIdx.x;

    __shared__ int s_r[LL];
    __shared__ int s_p[LL];
    __shared__ int s_red[LL];

    s_r[l] = rwrt[b * LL + l];
    s_p[l] = psg_in[b * LL + l];
    __syncthreads();

    // shift = sum(rwrt == 1)
    s_red[l] = (s_r[l] == 1) ? 1 : 0;
    __syncthreads();
    for (int s = LL / 2; s > 0; s >>= 1) {
        if (l < s) s_red[l] += s_red[l + s];
        __syncthreads();
    }
    const int shift = s_red[0];
    __syncthreads();

    // trunc for own position
    int pos   = ((l - shift) % LL + LL) % LL;
    int fm    = 1 - s_r[LL - 1 - pos];
    int psv   = (pos == 0) ? 1 : s_p[pos - 1];
    int trunc = fm * psv;

    // firstnz = min l with trunc != 0
    s_red[l] = (trunc != 0) ? l : LL;
    __syncthreads();
    for (int s = LL / 2; s > 0; s >>= 1) {
        if (l < s) s_red[l] = min(s_red[l], s_red[l + s]);
        __syncthreads();
    }
    const int firstnz = s_red[0];

    const int t = b * LL + l;

    // merge the 4 chunk partials + fp64 near-tie recheck
    float v1 = -INFINITY, v2 = -INFINITY;
    int   i1 = 0,         i2 = 1;
#pragma unroll
    for (int cc = 0; cc < CH; cc++) {
        int4 pr = g_part[t * CH + cc];
        top2_insert(__int_as_float(pr.x), pr.y, v1, i1, v2, i2);
        top2_insert(__int_as_float(pr.z), pr.w, v1, i1, v2, i2);
    }
    int win = i1;
    if (v1 - v2 < 0.02f) {
        double k1 = precise_key(logits[(size_t)t * VV + i1],
                                gu[(size_t)t * VV + i1]);
        double k2 = precise_key(logits[(size_t)t * VV + i2],
                                gu[(size_t)t * VV + i2]);
        if (k2 > k1 || (k2 == k1 && i2 < i1)) win = i2;
    }

    g_am[t] = (s_r[l] != 0 && win < AVV) ? win : -1;
    g_ps[t] = (l >= firstnz) ? trunc : -1;
}

// ---------------------------------------------------------------------------
// K3: pure gather. One float4 slot per thread, no smem, no barriers.
// grid = NT*ND4/NTH = 1536 blocks.
// ---------------------------------------------------------------------------
__global__ void __launch_bounds__(NTH)
gather_kernel(const float* __restrict__ W,
              float*       __restrict__ out) {
    const int idx = blockIdx.x * NTH + threadIdx.x;   // 0 .. NT*ND4-1
    const int t   = idx / ND4;
    const int d   = idx - t * ND4;

    const float4* W4 = (const float4*)W;
    int am = __ldg(&g_am[t]);
    int ps = __ldg(&g_ps[t]);

    float4 acc = make_float4(0.f, 0.f, 0.f, 0.f);
    if (am >= 0) acc = W4[(size_t)am * ND4 + d];
    if (ps >= 0) {
        float4 wv = W4[(size_t)ps * ND4 + d];
        acc.x += wv.x; acc.y += wv.y; acc.z += wv.z; acc.w += wv.w;
    }
    ((float4*)out)[idx] = acc;
}

// ---------------------------------------------------------------------------
extern "C" void kernel_launch(void* const* d_in, const int* in_sizes, int n_in,
                              void* d_out, int out_size) {
    const float* logits = (const float*)d_in[0];
    const float* gu     = (const float*)d_in[1];
    const float* W      = (const float*)d_in[2];
    const int*   rwrt   = (const int*)d_in[3];
    const int*   psg    = (const int*)d_in[4];
    float* out = (float*)d_out;

    scan_kernel<<<NT * CH, NTH>>>(logits, gu);
    decide_kernel<<<BB, LL>>>(logits, gu, rwrt, psg);
    gather_kernel<<<(NT * ND4) / NTH, NTH>>>(W, out);
}

// round 6
// speedup vs baseline: 1.0669x; 1.0669x over previous
#include <cuda_runtime.h>
#include <math.h>

#define BB 4
#define LL 512
#define VV 32128
#define AVV 32000
#define DD 768
#define NT (BB*LL)
#define NV4 (VV/4)      // 8032
#define ND4 (DD/4)      // 192
#define NTH 256
#define CH 4            // chunks per token
#define CV4 (NV4/CH)    // 2008 float4 per chunk

// Scratch (device globals; no allocation allowed)
__device__ int4         g_part[NT * CH]; // per (token,chunk) top-2
__device__ unsigned int g_cnt[NT];       // arrival counter (replay-safe via &3)
__device__ int          g_ps[NT];        // psg row (-1 = none)

// ---------------------------------------------------------------------------
// Exact coarse key: lo - log(-log u). Series path near u=1: winners have
// u ~ 1-3e-5 where __logf's ~1e-6 ABSOLUTE error would be catastrophic
// relative error on t = -log u. Abs key error bounded ~1.2e-4.
// ---------------------------------------------------------------------------
__device__ __forceinline__ float coarse_key(float lo, float u) {
    float w  = 1.0f - u;                 // exact for u > 0.5 (Sterbenz)
    float ts = fmaf(0.5f * w, w, w);     // w + w^2/2
    float tl = -__logf(u);
    float t  = (u > 0.99609375f) ? ts : tl;
    return lo - __logf(t);
}

__device__ __forceinline__ double precise_key(float lo, float u) {
    return (double)lo - log(-log((double)u));
}

__device__ __forceinline__ void ins2(float k, int j,
                                     float& v1, int& i1,
                                     float& v2, int& i2) {
    bool p = k > v1;
    float dv = p ? v1 : k;
    int   di = p ? i1 : j;
    if (p) { v1 = k; i1 = j; }
    if (dv > v2) { v2 = dv; i2 = di; }
}

__device__ __forceinline__ void top2_insert(float w, int j,
                                            float& v1, int& i1,
                                            float& v2, int& i2) {
    if (w > v1 || (w == v1 && j < i1)) {
        v2 = v1; i2 = i1; v1 = w; i1 = j;
    } else if (w > v2 || (w == v2 && j < i2)) {
        v2 = w; i2 = j;
    }
}

// ---------------------------------------------------------------------------
// K0: psg prep. One warp per batch, shuffle reductions only (~1us).
// ---------------------------------------------------------------------------
__global__ void __launch_bounds__(32)
psg_prep_kernel(const int* __restrict__ rwrt,
                const int* __restrict__ psg_in) {
    __shared__ int s_r[LL];
    __shared__ int s_p[LL];
    const int b    = blockIdx.x;
    const int lane = threadIdx.x;

    int cnt = 0;
#pragma unroll
    for (int k = 0; k < LL / 32; k++) {
        int l  = lane + 32 * k;
        int rv = rwrt[b * LL + l];
        s_r[l] = rv;
        s_p[l] = psg_in[b * LL + l];
        cnt += (rv == 1);
    }
    __syncwarp();
#pragma unroll
    for (int o = 16; o > 0; o >>= 1) cnt += __shfl_xor_sync(0xFFFFFFFFu, cnt, o);
    const int shift = cnt;

    int tr[LL / 32];
    int firstnz = LL;
#pragma unroll
    for (int k = 0; k < LL / 32; k++) {
        int l   = lane + 32 * k;
        int pos = ((l - shift) % LL + LL) % LL;
        int fm  = 1 - s_r[LL - 1 - pos];
        int psv = (pos == 0) ? 1 : s_p[pos - 1];
        int t   = fm * psv;
        tr[k] = t;
        if (t != 0) firstnz = min(firstnz, l);
    }
#pragma unroll
    for (int o = 16; o > 0; o >>= 1)
        firstnz = min(firstnz, __shfl_xor_sync(0xFFFFFFFFu, firstnz, o));

#pragma unroll
    for (int k = 0; k < LL / 32; k++) {
        int l = lane + 32 * k;
        g_ps[b * LL + l] = (l >= firstnz) ? tr[k] : -1;
    }
}

// ---------------------------------------------------------------------------
// K1: streaming scan with group-UB filter + fused last-block finish.
// ---------------------------------------------------------------------------
__global__ void __launch_bounds__(NTH, 8)
scan_kernel(const float* __restrict__ logits,
            const float* __restrict__ gu,
            const float* __restrict__ W,
            const int*   __restrict__ rwrt,
            float*       __restrict__ out) {
    const int blk = blockIdx.x;
    const int t   = blk >> 2;
    const int c   = blk & 3;
    const int tid = threadIdx.x;

    const float4* lg = (const float4*)(logits + (size_t)t * VV) + c * CV4;
    const float4* gg = (const float4*)(gu     + (size_t)t * VV) + c * CV4;
    const int jbase = c * CV4 * 4;

    float v1 = -INFINITY, v2 = -INFINITY;
    int   i1 = 0,         i2 = 1;

    // ---- seed: one exact float4 per lane, warp-wide 2nd-max -> thr ----
    {
        float4 a = __ldcs(lg + tid);
        float4 g = __ldcs(gg + tid);
        int base = jbase + 4 * tid;
        ins2(coarse_key(a.x, g.x), base + 0, v1, i1, v2, i2);
        ins2(coarse_key(a.y, g.y), base + 1, v1, i1, v2, i2);
        ins2(coarse_key(a.z, g.z), base + 2, v1, i1, v2, i2);
        ins2(coarse_key(a.w, g.w), base + 3, v1, i1, v2, i2);
    }
    float sa = v1, sb = v2;
#pragma unroll
    for (int off = 16; off > 0; off >>= 1) {
        float oa = __shfl_xor_sync(0xFFFFFFFFu, sa, off);
        float ob = __shfl_xor_sync(0xFFFFFFFFu, sb, off);
        float hi  = fmaxf(sa, oa);
        float lo2 = fmaxf(fminf(sa, oa), fmaxf(sb, ob));
        sa = hi; sb = lo2;
    }

    const float CC  = 8.2629582e-8f;     // ln2 / 2^23
    const float CBE = 88.029703f;        // 127*ln2 + EPS(1e-5)
    // thrm = (lower bound on global #2) - CBE
    float thrm = fmaxf(v2, sb) - CBE;

    // ---- main scan: ONE UB test per float4 ----
    // key_e <= lmax - ln2*l2a(1-umax) + slack; pass iff that > thr.
    for (int i = tid + NTH; i < CV4; i += NTH) {
        float4 a = __ldcs(lg + i);
        float4 g = __ldcs(gg + i);
        float umax = fmaxf(fmaxf(g.x, g.y), fmaxf(g.z, g.w));
        float lmax = fmaxf(fmaxf(a.x, a.y), fmaxf(a.z, a.w));
        float fb = (float)__float_as_int(1.0f - umax);
        if (fmaf(-CC, fb, lmax) > thrm) {
            int base = jbase + 4 * i;
            ins2(coarse_key(a.x, g.x), base + 0, v1, i1, v2, i2);
            ins2(coarse_key(a.y, g.y), base + 1, v1, i1, v2, i2);
            ins2(coarse_key(a.z, g.z), base + 2, v1, i1, v2, i2);
            ins2(coarse_key(a.w, g.w), base + 3, v1, i1, v2, i2);
            thrm = fmaxf(thrm, v2 - CBE);
        }
    }

    // ---- block reduction ----
    __shared__ float s_v1[NTH]; __shared__ int s_i1[NTH];
    __shared__ float s_v2[NTH]; __shared__ int s_i2[NTH];
    __shared__ int   s_fin[3];   // [0]=is_last, [1]=am, [2]=ps
    s_v1[tid] = v1; s_i1[tid] = i1;
    s_v2[tid] = v2; s_i2[tid] = i2;
    __syncthreads();
    for (int s = NTH / 2; s > 0; s >>= 1) {
        if (tid < s) {
            float w1 = s_v1[tid + s], w2 = s_v2[tid + s];
            int   j1 = s_i1[tid + s], j2 = s_i2[tid + s];
            float a1 = s_v1[tid],     a2 = s_v2[tid];
            int   c1 = s_i1[tid],     c2 = s_i2[tid];
            top2_insert(w1, j1, a1, c1, a2, c2);
            top2_insert(w2, j2, a1, c1, a2, c2);
            s_v1[tid] = a1; s_i1[tid] = c1;
            s_v2[tid] = a2; s_i2[tid] = c2;
        }
        __syncthreads();
    }
    if (tid == 0) {
        g_part[blk] = make_int4(__float_as_int(s_v1[0]), s_i1[0],
                                __float_as_int(s_v2[0]), s_i2[0]);
        __threadfence();
        unsigned int old = atomicAdd(&g_cnt[t], 1u);
        s_fin[0] = ((old & 3u) == 3u) ? 1 : 0;   // replay-safe: +4 per run
    }
    __syncthreads();
    if (!s_fin[0]) return;

    // ---- last block for this token: finish ----
    __threadfence();
    if (tid == 0) {
        float m1 = -INFINITY, m2 = -INFINITY;
        int   a1 = 0,         a2 = 1;
#pragma unroll
        for (int cc = 0; cc < CH; cc++) {
            int4 pr = __ldcg((int4*)&g_part[t * CH + cc]);
            top2_insert(__int_as_float(pr.x), pr.y, m1, a1, m2, a2);
            top2_insert(__int_as_float(pr.z), pr.w, m1, a1, m2, a2);
        }
        int win = a1;
        if (m1 - m2 < 0.02f) {
            double k1 = precise_key(logits[(size_t)t * VV + a1],
                                    gu[(size_t)t * VV + a1]);
            double k2 = precise_key(logits[(size_t)t * VV + a2],
                                    gu[(size_t)t * VV + a2]);
            if (k2 > k1 || (k2 == k1 && a2 < a1)) win = a2;
        }
        s_fin[1] = (rwrt[t] != 0 && win < AVV) ? win : -1;
        s_fin[2] = g_ps[t];
    }
    __syncthreads();

    if (tid < ND4) {
        const float4* W4 = (const float4*)W;
        int am = s_fin[1];
        int ps = s_fin[2];
        float4 acc = make_float4(0.f, 0.f, 0.f, 0.f);
        if (am >= 0) acc = W4[(size_t)am * ND4 + tid];
        if (ps >= 0) {
            float4 wv = W4[(size_t)ps * ND4 + tid];
            acc.x += wv.x; acc.y += wv.y; acc.z += wv.z; acc.w += wv.w;
        }
        ((float4*)out)[(size_t)t * ND4 + tid] = acc;
    }
}

// ---------------------------------------------------------------------------
extern "C" void kernel_launch(void* const* d_in, const int* in_sizes, int n_in,
                              void* d_out, int out_size) {
    const float* logits = (const float*)d_in[0];
    const float* gu     = (const float*)d_in[1];
    const float* W      = (const float*)d_in[2];
    const int*   rwrt   = (const int*)d_in[3];
    const int*   psg    = (const int*)d_in[4];
    float* out = (float*)d_out;

    psg_prep_kernel<<<BB, 32>>>(rwrt, psg);
    scan_kernel<<<NT * CH, NTH>>>(logits, gu, W, rwrt, out);
}